// round 15
// baseline (speedup 1.0000x reference)
#include <cuda_runtime.h>
#include <cuda_fp16.h>
#include <cstdint>

#define NTOT   100000
#define KNEI   16
#define XNIN   128
#define XEIN   64
#define XNOUT  128
#define KTOT   320      // 128 (x) + 128 (xnj) + 64 (xej)
#define AS     328      // smem row stride in halves: conflict-free for LDS/LDSM
#define CHUNK_ROWS 64
#define NCH    ((NTOT + CHUNK_ROWS - 1) / CHUNK_ROWS)   // 1563
#define GRID_G 152      // GB300: 152 SMs, 1 persistent CTA each

// Scratch (device globals — allocation-free per harness rules)
__device__ __half g_xh[(size_t)NTOT * XNIN];      // fp16 copy of x (25.6 MB)
__device__ __half g_A2[(size_t)NTOT * 192];       // fp16 [gather-mean(128) | e-mean(64)]
__device__ __half g_wh[XNOUT * KTOT];             // packed fp16 [Wc|Wn|We], row-major (n,k)

__device__ __forceinline__ uint32_t smem_u32(const void* p) {
    uint32_t a;
    asm("{ .reg .u64 t; cvta.to.shared.u64 t, %1; cvt.u32.u64 %0, t; }"
        : "=r"(a) : "l"(p));
    return a;
}

__device__ __forceinline__ void cp16(uint32_t dst, const void* src) {
    asm volatile("cp.async.cg.shared.global [%0], [%1], 16;"
                 :: "r"(dst), "l"(src));
}

// ---------------------------------------------------------------------------
// Kernel 1: quantize x -> fp16, pack weights -> fp16   (stream 0)
// ---------------------------------------------------------------------------
__global__ void prep_kernel(const float* __restrict__ x,
                            const float* __restrict__ Wc,
                            const float* __restrict__ Wn,
                            const float* __restrict__ We) {
    int tid = blockIdx.x * blockDim.x + threadIdx.x;
    int stride = gridDim.x * blockDim.x;

    const float4* x4 = (const float4*)x;
    __half2* xh2 = (__half2*)g_xh;
    const int total4 = NTOT * XNIN / 4;
    for (int i = tid; i < total4; i += stride) {
        float4 v = __ldcs(&x4[i]);
        xh2[2 * i]     = __floats2half2_rn(v.x, v.y);
        xh2[2 * i + 1] = __floats2half2_rn(v.z, v.w);
    }

    for (int i = tid; i < XNOUT * KTOT; i += stride) {
        int n = i / KTOT, k = i % KTOT;
        float w = (k < 128) ? Wc[n * 128 + k]
                : (k < 256) ? Wn[n * 128 + (k - 128)]
                            : We[n * 64 + (k - 256)];
        g_wh[i] = __float2half(w);
    }
}

// ---------------------------------------------------------------------------
// Kernel 2a: e-mean only (independent of prep!) — runs on side stream.
// Writes A2[r, 128:192]; disjoint bytes from gather's A2[r, 0:128].
// ---------------------------------------------------------------------------
__global__ void __launch_bounds__(256)
emean_kernel(const float* __restrict__ e) {
    const int lane   = threadIdx.x & 31;
    const int warpId = (blockIdx.x * blockDim.x + threadIdx.x) >> 5;
    const int nWarps = (gridDim.x * blockDim.x) >> 5;

    for (int r = warpId; r < NTOT; r += nWarps) {
        float2 ev[KNEI];
        const float2* ebase = (const float2*)(e + (size_t)r * (KNEI * XEIN)) + lane;
        #pragma unroll
        for (int k = 0; k < KNEI; k++)
            ev[k] = __ldcs(ebase + k * (XEIN / 2));

        float s0 = 0.f, s1 = 0.f;
        #pragma unroll
        for (int k = 0; k < KNEI; k++) { s0 += ev[k].x; s1 += ev[k].y; }

        *(__half2*)&g_A2[(size_t)r * 192 + 128 + lane * 2] =
            __floats2half2_rn(s0 * 0.0625f, s1 * 0.0625f);
    }
}

// ---------------------------------------------------------------------------
// Kernel 2b: gather-mean only (needs g_xh -> after prep), stream 0.
// R7 form with ij software pipeline. Writes A2[r, 0:128].
// ---------------------------------------------------------------------------
__global__ void __launch_bounds__(256)
gather_kernel(const int* __restrict__ ij) {
    const int lane   = threadIdx.x & 31;
    const int warpId = (blockIdx.x * blockDim.x + threadIdx.x) >> 5;
    const int nWarps = (gridDim.x * blockDim.x) >> 5;

    int r = warpId;
    int idx = 0;
    if (r < NTOT && lane < KNEI)
        idx = __ldcs(&ij[((size_t)r * KNEI + lane) * 2]);

    for (; r < NTOT; r += nWarps) {
        const int rn = r + nWarps;
        int idx_next = 0;
        if (rn < NTOT && lane < KNEI)
            idx_next = __ldcs(&ij[((size_t)rn * KNEI + lane) * 2]);

        uint2 vals[KNEI];
        #pragma unroll
        for (int k = 0; k < KNEI; k++) {
            int nb = __shfl_sync(0xffffffffu, idx, k);
            nb = (nb < 0) ? 0 : ((nb >= NTOT) ? (NTOT - 1) : nb);
            vals[k] = *(const uint2*)&g_xh[(size_t)nb * XNIN + lane * 4];
        }

        float f0 = 0.f, f1 = 0.f, f2 = 0.f, f3 = 0.f;
        #pragma unroll
        for (int k = 0; k < KNEI; k++) {
            float2 a = __half22float2(*(__half2*)&vals[k].x);
            float2 b = __half22float2(*(__half2*)&vals[k].y);
            f0 += a.x; f1 += a.y; f2 += b.x; f3 += b.y;
        }

        uint2 gpack;
        *(__half2*)&gpack.x = __floats2half2_rn(f0 * 0.0625f, f1 * 0.0625f);
        *(__half2*)&gpack.y = __floats2half2_rn(f2 * 0.0625f, f3 * 0.0625f);
        *(uint2*)&g_A2[(size_t)r * 192 + lane * 4] = gpack;

        idx = idx_next;
    }
}

// ---------------------------------------------------------------------------
// Kernel 3: persistent double-buffered GEMM with ldmatrix fragment loads (R12)
// ---------------------------------------------------------------------------
#define LDSM4(r0, r1, r2, r3, addr)                                          \
    asm volatile("ldmatrix.sync.aligned.m8n8.x4.shared.b16 {%0,%1,%2,%3}, [%4];" \
                 : "=r"(r0), "=r"(r1), "=r"(r2), "=r"(r3) : "r"(addr))

extern __shared__ __half smem[];

__global__ void __launch_bounds__(512, 1)
gemm_kernel(float* __restrict__ out) {
    __half* Wsm = smem;                                   // [128][AS]
    __half* Ab0 = smem + 128 * AS;                        // [64][AS]
    __half* Ab1 = smem + 128 * AS + CHUNK_ROWS * AS;      // [64][AS]
    const uint32_t abase[2] = { smem_u32(Ab0), smem_u32(Ab1) };
    const uint32_t wbase    = smem_u32(Wsm);

    const int tid  = threadIdx.x;
    const int lane = tid & 31;
    const int warp = tid >> 5;

    {
        const int4* wsrc = (const int4*)g_wh;   // 5120 int4
        for (int i = tid; i < 5120; i += 512) {
            int row = i / 40, c = i % 40;
            *(int4*)&Wsm[row * AS + c * 8] = wsrc[i];
        }
    }

    int c = blockIdx.x;
    {
        int base = c * CHUNK_ROWS;
        for (int i = tid; i < 2560; i += 512) {        // 64 rows * 40 int4
            int row = i / 40, cc = i % 40;
            int r = base + row; if (r > NTOT - 1) r = NTOT - 1;
            const void* src = (cc < 16)
                ? (const void*)&g_xh[(size_t)r * XNIN + cc * 8]
                : (const void*)&g_A2[(size_t)r * 192 + (cc - 16) * 8];
            cp16(abase[0] + (uint32_t)(row * AS + cc * 8) * 2u, src);
        }
    }
    asm volatile("cp.async.commit_group;" ::: "memory");

    const int g  = lane >> 2;
    const int tg = lane & 3;
    const int mq = warp >> 2;     // 0..3 : 16-row m-tile within chunk
    const int nq = warp & 3;      // 0..3 : 32-col n-quarter
    const int wm = mq * 16;

    const uint32_t a_off = (uint32_t)((wm + (lane & 15)) * AS + (lane >> 4) * 8) * 2u;
    const uint32_t b_row = (uint32_t)(nq * 32 + (lane & 7) + ((lane >> 4) & 1) * 8);
    const uint32_t b_off = (b_row * AS + ((lane >> 3) & 1) * 8) * 2u;
    const uint32_t b_addr0 = wbase + b_off;
    const uint32_t b_addr1 = wbase + b_off + (uint32_t)(16 * AS) * 2u;

    int buf = 0;
    for (; c < NCH; c += GRID_G) {
        int cn = c + GRID_G;
        if (cn < NCH) {
            int base = cn * CHUNK_ROWS;
            for (int i = tid; i < 2560; i += 512) {
                int row = i / 40, cc = i % 40;
                int r = base + row; if (r > NTOT - 1) r = NTOT - 1;
                const void* src = (cc < 16)
                    ? (const void*)&g_xh[(size_t)r * XNIN + cc * 8]
                    : (const void*)&g_A2[(size_t)r * 192 + (cc - 16) * 8];
                cp16(abase[buf ^ 1] + (uint32_t)(row * AS + cc * 8) * 2u, src);
            }
        }
        asm volatile("cp.async.commit_group;" ::: "memory");
        asm volatile("cp.async.wait_group 1;" ::: "memory");
        __syncthreads();

        const uint32_t a_addr = abase[buf] + a_off;
        float acc[4][4];
        #pragma unroll
        for (int t = 0; t < 4; t++)
            acc[t][0] = acc[t][1] = acc[t][2] = acc[t][3] = 0.f;

        #pragma unroll 4
        for (int k0 = 0; k0 < KTOT; k0 += 16) {
            uint32_t a0, a1, a2, a3;
            LDSM4(a0, a1, a2, a3, a_addr + k0 * 2);
            uint32_t b00, b01, b10, b11;
            LDSM4(b00, b01, b10, b11, b_addr0 + k0 * 2);
            uint32_t b20, b21, b30, b31;
            LDSM4(b20, b21, b30, b31, b_addr1 + k0 * 2);

            asm volatile(
                "mma.sync.aligned.m16n8k16.row.col.f32.f16.f16.f32 "
                "{%0,%1,%2,%3},{%4,%5,%6,%7},{%8,%9},{%0,%1,%2,%3};\n"
                : "+f"(acc[0][0]), "+f"(acc[0][1]), "+f"(acc[0][2]), "+f"(acc[0][3])
                : "r"(a0), "r"(a1), "r"(a2), "r"(a3), "r"(b00), "r"(b01));
            asm volatile(
                "mma.sync.aligned.m16n8k16.row.col.f32.f16.f16.f32 "
                "{%0,%1,%2,%3},{%4,%5,%6,%7},{%8,%9},{%0,%1,%2,%3};\n"
                : "+f"(acc[1][0]), "+f"(acc[1][1]), "+f"(acc[1][2]), "+f"(acc[1][3])
                : "r"(a0), "r"(a1), "r"(a2), "r"(a3), "r"(b10), "r"(b11));
            asm volatile(
                "mma.sync.aligned.m16n8k16.row.col.f32.f16.f16.f32 "
                "{%0,%1,%2,%3},{%4,%5,%6,%7},{%8,%9},{%0,%1,%2,%3};\n"
                : "+f"(acc[2][0]), "+f"(acc[2][1]), "+f"(acc[2][2]), "+f"(acc[2][3])
                : "r"(a0), "r"(a1), "r"(a2), "r"(a3), "r"(b20), "r"(b21));
            asm volatile(
                "mma.sync.aligned.m16n8k16.row.col.f32.f16.f16.f32 "
                "{%0,%1,%2,%3},{%4,%5,%6,%7},{%8,%9},{%0,%1,%2,%3};\n"
                : "+f"(acc[3][0]), "+f"(acc[3][1]), "+f"(acc[3][2]), "+f"(acc[3][3])
                : "r"(a0), "r"(a1), "r"(a2), "r"(a3), "r"(b30), "r"(b31));
        }

        int rbase = c * CHUNK_ROWS;
        #pragma unroll
        for (int t = 0; t < 4; t++) {
            int col  = nq * 32 + t * 8 + tg * 2;
            int row0 = rbase + wm + g;
            int row1 = row0 + 8;
            if (row0 < NTOT) {
                float2 v;
                v.x = fmaxf(acc[t][0], 0.f);
                v.y = fmaxf(acc[t][1], 0.f);
                __stcs((float2*)&out[(size_t)row0 * XNOUT + col], v);
            }
            if (row1 < NTOT) {
                float2 v;
                v.x = fmaxf(acc[t][2], 0.f);
                v.y = fmaxf(acc[t][3], 0.f);
                __stcs((float2*)&out[(size_t)row1 * XNOUT + col], v);
            }
        }

        __syncthreads();
        buf ^= 1;
    }
}

// ---------------------------------------------------------------------------
// Launcher: fork e-mean onto a side stream (independent of prep/gather),
// join before gemm. Stream/event handles are static; identical work per call.
// ---------------------------------------------------------------------------
extern "C" void kernel_launch(void* const* d_in, const int* in_sizes, int n_in,
                              void* d_out, int out_size) {
    const float* x  = (const float*)d_in[0];
    const float* e  = (const float*)d_in[1];
    const int*   ij = (const int*)d_in[2];     // int32 (JAX x64 disabled)
    const float* Wc = (const float*)d_in[3];
    const float* Wn = (const float*)d_in[4];
    const float* We = (const float*)d_in[5];
    float* out = (float*)d_out;
    (void)in_sizes; (void)n_in; (void)out_size;

    static cudaStream_t s2 = nullptr;
    static cudaEvent_t evFork = nullptr, evJoin = nullptr;
    if (s2 == nullptr) {
        cudaStreamCreateWithFlags(&s2, cudaStreamNonBlocking);
        cudaEventCreateWithFlags(&evFork, cudaEventDisableTiming);
        cudaEventCreateWithFlags(&evJoin, cudaEventDisableTiming);
    }

    // fork: e-mean on side stream (no dependency on prep)
    cudaEventRecord(evFork, 0);
    cudaStreamWaitEvent(s2, evFork, 0);
    emean_kernel<<<2048, 256, 0, s2>>>(e);
    cudaEventRecord(evJoin, s2);

    // main stream: prep -> gather
    prep_kernel<<<2048, 256>>>(x, Wc, Wn, We);
    gather_kernel<<<2048, 256>>>(ij);

    // join, then GEMM
    cudaStreamWaitEvent(0, evJoin, 0);
    const int smem_bytes = (128 + 2 * CHUNK_ROWS) * AS * (int)sizeof(__half); // 167936
    cudaFuncSetAttribute(gemm_kernel,
                         cudaFuncAttributeMaxDynamicSharedMemorySize, smem_bytes);
    gemm_kernel<<<GRID_G, 512, smem_bytes>>>(out);
}

// round 17
// speedup vs baseline: 1.1995x; 1.1995x over previous
#include <cuda_runtime.h>
#include <cuda_fp16.h>
#include <cstdint>

#define NTOT   100000
#define KNEI   16
#define XNIN   128
#define XEIN   64
#define XNOUT  128
#define KTOT   320      // 128 (x) + 128 (xnj) + 64 (xej)
#define AS     328      // smem row stride in halves: conflict-free for LDS/LDSM
#define CHUNK_ROWS 64
#define NCH    ((NTOT + CHUNK_ROWS - 1) / CHUNK_ROWS)   // 1563
#define GRID_G 152      // GB300: 152 SMs, 1 persistent CTA each

// Scratch (device globals — allocation-free per harness rules)
__device__ __half g_xh[(size_t)NTOT * XNIN];      // fp16 copy of x (25.6 MB)
__device__ __half g_A2[(size_t)NTOT * 192];       // fp16 [gather-mean(128) | e-mean(64)]
__device__ __half g_wh[XNOUT * KTOT];             // packed fp16 [Wc|Wn|We], row-major (n,k)

__device__ __forceinline__ uint32_t smem_u32(const void* p) {
    uint32_t a;
    asm("{ .reg .u64 t; cvta.to.shared.u64 t, %1; cvt.u32.u64 %0, t; }"
        : "=r"(a) : "l"(p));
    return a;
}

__device__ __forceinline__ void cp16(uint32_t dst, const void* src) {
    asm volatile("cp.async.cg.shared.global [%0], [%1], 16;"
                 :: "r"(dst), "l"(src));
}

// ---------------------------------------------------------------------------
// Kernel 1: quantize x -> fp16, pack weights -> fp16
// ---------------------------------------------------------------------------
__global__ void prep_kernel(const float* __restrict__ x,
                            const float* __restrict__ Wc,
                            const float* __restrict__ Wn,
                            const float* __restrict__ We) {
    int tid = blockIdx.x * blockDim.x + threadIdx.x;
    int stride = gridDim.x * blockDim.x;

    const float4* x4 = (const float4*)x;
    __half2* xh2 = (__half2*)g_xh;
    const int total4 = NTOT * XNIN / 4;
    for (int i = tid; i < total4; i += stride) {
        float4 v = __ldcs(&x4[i]);
        xh2[2 * i]     = __floats2half2_rn(v.x, v.y);
        xh2[2 * i + 1] = __floats2half2_rn(v.z, v.w);
    }

    for (int i = tid; i < XNOUT * KTOT; i += stride) {
        int n = i / KTOT, k = i % KTOT;
        float w = (k < 128) ? Wc[n * 128 + k]
                : (k < 256) ? Wn[n * 128 + (k - 128)]
                            : We[n * 64 + (k - 256)];
        g_wh[i] = __float2half(w);
    }
}

// ---------------------------------------------------------------------------
// Kernel 2: build A2 (R7/R12 form — at its e-stream DRAM floor, ~67us)
// ---------------------------------------------------------------------------
__global__ void __launch_bounds__(256)
build_kernel(const float* __restrict__ e,
             const int* __restrict__ ij) {
    const int lane   = threadIdx.x & 31;
    const int warpId = (blockIdx.x * blockDim.x + threadIdx.x) >> 5;
    const int nWarps = (gridDim.x * blockDim.x) >> 5;

    int r = warpId;
    int idx = 0;
    if (r < NTOT && lane < KNEI)
        idx = __ldcs(&ij[((size_t)r * KNEI + lane) * 2]);

    for (; r < NTOT; r += nWarps) {
        const int rn = r + nWarps;
        int idx_next = 0;
        if (rn < NTOT && lane < KNEI)
            idx_next = __ldcs(&ij[((size_t)rn * KNEI + lane) * 2]);

        float2 evals[KNEI];
        const float2* ebase = (const float2*)(e + (size_t)r * (KNEI * XEIN)) + lane;
        #pragma unroll
        for (int k = 0; k < KNEI; k++)
            evals[k] = __ldcs(ebase + k * (XEIN / 2));

        uint2 vals[KNEI];
        #pragma unroll
        for (int k = 0; k < KNEI; k++) {
            int nb = __shfl_sync(0xffffffffu, idx, k);
            nb = (nb < 0) ? 0 : ((nb >= NTOT) ? (NTOT - 1) : nb);
            vals[k] = *(const uint2*)&g_xh[(size_t)nb * XNIN + lane * 4];
        }

        float f0 = 0.f, f1 = 0.f, f2 = 0.f, f3 = 0.f;
        #pragma unroll
        for (int k = 0; k < KNEI; k++) {
            float2 a = __half22float2(*(__half2*)&vals[k].x);
            float2 b = __half22float2(*(__half2*)&vals[k].y);
            f0 += a.x; f1 += a.y; f2 += b.x; f3 += b.y;
        }
        float s0 = 0.f, s1 = 0.f;
        #pragma unroll
        for (int k = 0; k < KNEI; k++) { s0 += evals[k].x; s1 += evals[k].y; }

        __half* arow = &g_A2[(size_t)r * 192];
        uint2 gpack;
        *(__half2*)&gpack.x = __floats2half2_rn(f0 * 0.0625f, f1 * 0.0625f);
        *(__half2*)&gpack.y = __floats2half2_rn(f2 * 0.0625f, f3 * 0.0625f);
        *(uint2*)&arow[lane * 4] = gpack;
        *(__half2*)&arow[128 + lane * 2] = __floats2half2_rn(s0 * 0.0625f, s1 * 0.0625f);

        idx = idx_next;
    }
}

// ---------------------------------------------------------------------------
// Kernel 3: persistent double-buffered GEMM, m32n32 warp tiles (8 warps).
// Crossbar traffic per chunk drops to the MMA floor (B redundancy 4 -> 2).
// ---------------------------------------------------------------------------
#define LDSM4(r0, r1, r2, r3, addr)                                          \
    asm volatile("ldmatrix.sync.aligned.m8n8.x4.shared.b16 {%0,%1,%2,%3}, [%4];" \
                 : "=r"(r0), "=r"(r1), "=r"(r2), "=r"(r3) : "r"(addr))

#define MMA16816(d, a0, a1, a2, a3, b0, b1)                                  \
    asm volatile(                                                            \
        "mma.sync.aligned.m16n8k16.row.col.f32.f16.f16.f32 "                 \
        "{%0,%1,%2,%3},{%4,%5,%6,%7},{%8,%9},{%0,%1,%2,%3};\n"               \
        : "+f"(d[0]), "+f"(d[1]), "+f"(d[2]), "+f"(d[3])                     \
        : "r"(a0), "r"(a1), "r"(a2), "r"(a3), "r"(b0), "r"(b1))

extern __shared__ __half smem[];

__global__ void __launch_bounds__(256, 1)
gemm_kernel(float* __restrict__ out) {
    __half* Wsm = smem;                                   // [128][AS]
    __half* Ab0 = smem + 128 * AS;                        // [64][AS]
    __half* Ab1 = smem + 128 * AS + CHUNK_ROWS * AS;      // [64][AS]
    const uint32_t abase[2] = { smem_u32(Ab0), smem_u32(Ab1) };
    const uint32_t wbase    = smem_u32(Wsm);

    const int tid  = threadIdx.x;
    const int lane = tid & 31;
    const int warp = tid >> 5;

    // ---- W: packed weights -> smem (once per persistent CTA) ----
    {
        const int4* wsrc = (const int4*)g_wh;   // 5120 int4
        for (int i = tid; i < 5120; i += 256) {
            int row = i / 40, c = i % 40;
            *(int4*)&Wsm[row * AS + c * 8] = wsrc[i];
        }
    }

    // ---- prologue: async-load first chunk into buf 0 ----
    int c = blockIdx.x;
    {
        int base = c * CHUNK_ROWS;
        for (int i = tid; i < 2560; i += 256) {        // 64 rows * 40 int4
            int row = i / 40, cc = i % 40;
            int r = base + row; if (r > NTOT - 1) r = NTOT - 1;
            const void* src = (cc < 16)
                ? (const void*)&g_xh[(size_t)r * XNIN + cc * 8]
                : (const void*)&g_A2[(size_t)r * 192 + (cc - 16) * 8];
            cp16(abase[0] + (uint32_t)(row * AS + cc * 8) * 2u, src);
        }
    }
    asm volatile("cp.async.commit_group;" ::: "memory");

    const int g  = lane >> 2;
    const int tg = lane & 3;
    const int mh = warp >> 2;     // 0..1 : 32-row m-tile within chunk
    const int nq = warp & 3;      // 0..3 : 32-col n-quarter
    const int wm = mh * 32;

    // ldmatrix lane offsets (bytes)
    // A: two m16k16 tiles at rows wm / wm+16
    const uint32_t a_off0 = (uint32_t)((wm + (lane & 15)) * AS + (lane >> 4) * 8) * 2u;
    const uint32_t a_off1 = a_off0 + (uint32_t)(16 * AS) * 2u;
    // B: two n16k16 tiles at rows nq*32 / nq*32+16
    const uint32_t b_row = (uint32_t)(nq * 32 + (lane & 7) + ((lane >> 4) & 1) * 8);
    const uint32_t b_off = (b_row * AS + ((lane >> 3) & 1) * 8) * 2u;
    const uint32_t b_addr0 = wbase + b_off;
    const uint32_t b_addr1 = wbase + b_off + (uint32_t)(16 * AS) * 2u;

    int buf = 0;
    for (; c < NCH; c += GRID_G) {
        // ---- prefetch next chunk into the other buffer ----
        int cn = c + GRID_G;
        if (cn < NCH) {
            int base = cn * CHUNK_ROWS;
            for (int i = tid; i < 2560; i += 256) {
                int row = i / 40, cc = i % 40;
                int r = base + row; if (r > NTOT - 1) r = NTOT - 1;
                const void* src = (cc < 16)
                    ? (const void*)&g_xh[(size_t)r * XNIN + cc * 8]
                    : (const void*)&g_A2[(size_t)r * 192 + (cc - 16) * 8];
                cp16(abase[buf ^ 1] + (uint32_t)(row * AS + cc * 8) * 2u, src);
            }
        }
        asm volatile("cp.async.commit_group;" ::: "memory");
        asm volatile("cp.async.wait_group 1;" ::: "memory");
        __syncthreads();

        // ---- MMA on current buffer: m32 x n32 per warp ----
        const uint32_t aa0 = abase[buf] + a_off0;
        const uint32_t aa1 = abase[buf] + a_off1;
        float acc[8][4];    // [mhalf*4 + n8tile][4]
        #pragma unroll
        for (int t = 0; t < 8; t++)
            acc[t][0] = acc[t][1] = acc[t][2] = acc[t][3] = 0.f;

        #pragma unroll 2
        for (int k0 = 0; k0 < KTOT; k0 += 16) {
            uint32_t p0, p1, p2, p3, q0, q1, q2, q3;
            LDSM4(p0, p1, p2, p3, aa0 + k0 * 2);          // A rows wm..wm+15
            LDSM4(q0, q1, q2, q3, aa1 + k0 * 2);          // A rows wm+16..wm+31
            uint32_t b00, b01, b10, b11, b20, b21, b30, b31;
            LDSM4(b00, b01, b10, b11, b_addr0 + k0 * 2);  // B n8 tiles 0,1
            LDSM4(b20, b21, b30, b31, b_addr1 + k0 * 2);  // B n8 tiles 2,3

            MMA16816(acc[0], p0, p1, p2, p3, b00, b01);
            MMA16816(acc[1], p0, p1, p2, p3, b10, b11);
            MMA16816(acc[2], p0, p1, p2, p3, b20, b21);
            MMA16816(acc[3], p0, p1, p2, p3, b30, b31);
            MMA16816(acc[4], q0, q1, q2, q3, b00, b01);
            MMA16816(acc[5], q0, q1, q2, q3, b10, b11);
            MMA16816(acc[6], q0, q1, q2, q3, b20, b21);
            MMA16816(acc[7], q0, q1, q2, q3, b30, b31);
        }

        // ---- store with relu ----
        int rbase = c * CHUNK_ROWS + wm;
        #pragma unroll
        for (int half = 0; half < 2; half++) {
            #pragma unroll
            for (int t = 0; t < 4; t++) {
                const float* a = acc[half * 4 + t];
                int col  = nq * 32 + t * 8 + tg * 2;
                int row0 = rbase + half * 16 + g;
                int row1 = row0 + 8;
                if (row0 < NTOT) {
                    float2 v;
                    v.x = fmaxf(a[0], 0.f);
                    v.y = fmaxf(a[1], 0.f);
                    __stcs((float2*)&out[(size_t)row0 * XNOUT + col], v);
                }
                if (row1 < NTOT) {
                    float2 v;
                    v.x = fmaxf(a[2], 0.f);
                    v.y = fmaxf(a[3], 0.f);
                    __stcs((float2*)&out[(size_t)row1 * XNOUT + col], v);
                }
            }
        }

        __syncthreads();   // all smem reads of this buffer done before reuse
        buf ^= 1;
    }
}

// ---------------------------------------------------------------------------
extern "C" void kernel_launch(void* const* d_in, const int* in_sizes, int n_in,
                              void* d_out, int out_size) {
    const float* x  = (const float*)d_in[0];
    const float* e  = (const float*)d_in[1];
    const int*   ij = (const int*)d_in[2];     // int32 (JAX x64 disabled)
    const float* Wc = (const float*)d_in[3];
    const float* Wn = (const float*)d_in[4];
    const float* We = (const float*)d_in[5];
    float* out = (float*)d_out;
    (void)in_sizes; (void)n_in; (void)out_size;

    prep_kernel<<<2048, 256>>>(x, Wc, Wn, We);

    build_kernel<<<2048, 256>>>(e, ij);

    const int smem_bytes = (128 + 2 * CHUNK_ROWS) * AS * (int)sizeof(__half); // 167936
    cudaFuncSetAttribute(gemm_kernel,
                         cudaFuncAttributeMaxDynamicSharedMemorySize, smem_bytes);
    gemm_kernel<<<GRID_G, 256, smem_bytes>>>(out);
}